// round 1
// baseline (speedup 1.0000x reference)
#include <cuda_runtime.h>
#include <math.h>

#define K_DIM 256
#define H_DIM 256
#define OUT_DIM 512
#define G_DIM 256
#define TILE_M 32
#define XS_STRIDE 260   // 32x260 floats, 16B-aligned rows, bank-skewed
#define WS_STRIDE 36    // 256x36 floats staging for a 32-wide k-chunk

// Device scratch (no allocations allowed)
__device__ float d_W1[H_DIM * K_DIM];
__device__ float d_W2[H_DIM * H_DIM];
__device__ float d_W3[OUT_DIM * H_DIM];
__device__ float d_Wc[OUT_DIM * K_DIM];
__device__ float d_GAMMA[G_DIM * H_DIM];
__device__ float d_BETA[G_DIM * H_DIM];

// ---------------------------------------------------------------------------
// Weight normalization: W[r] = v[r] * g[r] / ||v[r]||
// one block per row, 256 threads (K == 256 for all weight matrices)
// ---------------------------------------------------------------------------
__global__ void wn_kernel(const float* __restrict__ v,
                          const float* __restrict__ g,
                          int which) {
    float* W = (which == 0) ? d_Wc : (which == 1) ? d_W1 : (which == 2) ? d_W2 : d_W3;
    int r = blockIdx.x, t = threadIdx.x;
    float x = v[r * K_DIM + t];
    float ss = x * x;
#pragma unroll
    for (int o = 16; o; o >>= 1) ss += __shfl_xor_sync(0xffffffffu, ss, o);
    __shared__ float red[8];
    __shared__ float s_scale;
    if ((t & 31) == 0) red[t >> 5] = ss;
    __syncthreads();
    if (t == 0) {
        float tot = 0.f;
#pragma unroll
        for (int i = 0; i < 8; i++) tot += red[i];
        s_scale = g[r] / sqrtf(tot);
    }
    __syncthreads();
    W[r * K_DIM + t] = x * s_scale;
}

// ---------------------------------------------------------------------------
// FiLM table: gb = cond @ Wc^T + b_cond ; gamma = gb[:, :256] + 1 ; beta = gb[:, 256:]
// one block per group g (256 blocks), 256 threads; each thread 2 dots of length 256
// ---------------------------------------------------------------------------
__global__ void film_kernel(const float* __restrict__ cond,
                            const float* __restrict__ b_cond) {
    __shared__ float cs[K_DIM];
    int g = blockIdx.x, t = threadIdx.x;
    cs[t] = cond[g * K_DIM + t];
    __syncthreads();
    const float* w0 = d_Wc + (size_t)t * K_DIM;
    const float* w1 = d_Wc + (size_t)(t + 256) * K_DIM;
    float a0 = 0.f, a1 = 0.f;
#pragma unroll 8
    for (int k = 0; k < K_DIM; k++) {
        float c = cs[k];
        a0 = fmaf(c, w0[k], a0);
        a1 = fmaf(c, w1[k], a1);
    }
    d_GAMMA[g * H_DIM + t] = a0 + b_cond[t] + 1.0f;
    d_BETA[g * H_DIM + t]  = a1 + b_cond[t + 256];
}

// ---------------------------------------------------------------------------
// Register-blocked smem GEMM: C[32 x 256] = A[32 x 256] @ Wg[256 x 256]^T
// A in smem (stride XS_STRIDE). Wg in global (L2-resident), staged in 32-wide
// k-chunks into Ws. 256 threads as 16x16; each thread owns 2 m-rows x 16 h-cols.
// ---------------------------------------------------------------------------
__device__ __forceinline__ void gemm_tile(const float* __restrict__ Wg,
                                          const float* __restrict__ A,
                                          float* __restrict__ Ws,
                                          float acc[2][16], int tid) {
    const int trow = tid >> 4, tcol = tid & 15;
    const int lh = tid >> 3, lq = tid & 7;
#pragma unroll
    for (int i = 0; i < 2; i++)
#pragma unroll
        for (int j = 0; j < 16; j++) acc[i][j] = 0.f;

#pragma unroll 1
    for (int k0 = 0; k0 < K_DIM; k0 += 32) {
        __syncthreads();  // protect Ws from previous chunk / previous phase
#pragma unroll
        for (int r = 0; r < 8; r++) {
            int hh = lh + 32 * r;
            float4 w4 = *reinterpret_cast<const float4*>(Wg + (size_t)hh * K_DIM + k0 + lq * 4);
            *reinterpret_cast<float4*>(Ws + hh * WS_STRIDE + lq * 4) = w4;
        }
        __syncthreads();
        const float* a0p = A + (trow * 2 + 0) * XS_STRIDE + k0;
        const float* a1p = A + (trow * 2 + 1) * XS_STRIDE + k0;
#pragma unroll
        for (int kk = 0; kk < 32; kk += 4) {
            float4 a0 = *reinterpret_cast<const float4*>(a0p + kk);
            float4 a1 = *reinterpret_cast<const float4*>(a1p + kk);
#pragma unroll
            for (int j = 0; j < 16; j++) {
                float4 b = *reinterpret_cast<const float4*>(Ws + (tcol + 16 * j) * WS_STRIDE + kk);
                acc[0][j] = fmaf(a0.x, b.x, acc[0][j]);
                acc[0][j] = fmaf(a0.y, b.y, acc[0][j]);
                acc[0][j] = fmaf(a0.z, b.z, acc[0][j]);
                acc[0][j] = fmaf(a0.w, b.w, acc[0][j]);
                acc[1][j] = fmaf(a1.x, b.x, acc[1][j]);
                acc[1][j] = fmaf(a1.y, b.y, acc[1][j]);
                acc[1][j] = fmaf(a1.z, b.z, acc[1][j]);
                acc[1][j] = fmaf(a1.w, b.w, acc[1][j]);
            }
        }
    }
}

// ---------------------------------------------------------------------------
// Fused main kernel: GEMM1 -> layernorm -> FiLM -> relu -> GEMM2(+b2,relu)
//                    -> GEMM3 (two 256-wide halves, +b3) -> coalesced store
// ---------------------------------------------------------------------------
__global__ void __launch_bounds__(256, 2)
fused_kernel(const float* __restrict__ x,
             const int* __restrict__ batch_ids,
             const float* __restrict__ b2,
             const float* __restrict__ b3,
             float* __restrict__ out, int N) {
    extern __shared__ float smem[];
    float* Xs = smem;                           // TILE_M * XS_STRIDE
    float* Hs = smem + TILE_M * XS_STRIDE;      // TILE_M * XS_STRIDE
    float* Ws = Hs + TILE_M * XS_STRIDE;        // 256 * WS_STRIDE

    const int tid = threadIdx.x;
    const int row0 = blockIdx.x * TILE_M;
    const int trow = tid >> 4, tcol = tid & 15;

    // cooperative X-tile load (float4, coalesced)
    {
        int m = tid >> 3, q = tid & 7;
        int row = row0 + m;
        const float4 z4 = make_float4(0.f, 0.f, 0.f, 0.f);
#pragma unroll
        for (int r = 0; r < 8; r++) {
            int c4 = q + 8 * r;
            float4 v4 = (row < N)
                ? *reinterpret_cast<const float4*>(x + (size_t)row * K_DIM + c4 * 4)
                : z4;
            *reinterpret_cast<float4*>(Xs + m * XS_STRIDE + c4 * 4) = v4;
        }
    }
    __syncthreads();

    float acc[2][16];

    // ---- GEMM1: Hs_pre = Xs @ W1^T ----
    gemm_tile(d_W1, Xs, Ws, acc, tid);
#pragma unroll
    for (int i = 0; i < 2; i++)
#pragma unroll
        for (int j = 0; j < 16; j++)
            Hs[(trow * 2 + i) * XS_STRIDE + tcol + 16 * j] = acc[i][j];
    __syncthreads();

    // ---- layernorm + FiLM + relu, in place on Hs (warp w -> rows 4w..4w+3)
    {
        int w = tid >> 5, l = tid & 31;
#pragma unroll
        for (int mm = 0; mm < 4; mm++) {
            int m = w * 4 + mm;
            float v[8];
            float s = 0.f, ss = 0.f;
#pragma unroll
            for (int p = 0; p < 8; p++) {
                v[p] = Hs[m * XS_STRIDE + l + 32 * p];
                s += v[p];
                ss = fmaf(v[p], v[p], ss);
            }
#pragma unroll
            for (int o = 16; o; o >>= 1) {
                s  += __shfl_xor_sync(0xffffffffu, s, o);
                ss += __shfl_xor_sync(0xffffffffu, ss, o);
            }
            float mu   = s * (1.f / 256.f);
            float var  = ss * (1.f / 256.f) - mu * mu;
            float rstd = rsqrtf(var + 1e-5f);
            int row = row0 + m;
            int bid = (row < N) ? batch_ids[row] : 0;
            const float* gp = d_GAMMA + (size_t)bid * H_DIM;
            const float* bp = d_BETA  + (size_t)bid * H_DIM;
#pragma unroll
            for (int p = 0; p < 8; p++) {
                int h = l + 32 * p;
                float t2 = fmaf((v[p] - mu) * rstd, gp[h], bp[h]);
                Hs[m * XS_STRIDE + h] = fmaxf(t2, 0.f);
            }
        }
    }
    // gemm_tile's leading __syncthreads orders Hs writes before reads

    // ---- GEMM2: Xs = relu(Hs @ W2^T + b2) ----
    gemm_tile(d_W2, Hs, Ws, acc, tid);
#pragma unroll
    for (int i = 0; i < 2; i++)
#pragma unroll
        for (int j = 0; j < 16; j++) {
            int h = tcol + 16 * j;
            Xs[(trow * 2 + i) * XS_STRIDE + h] = fmaxf(acc[i][j] + b2[h], 0.f);
        }

    // ---- GEMM3: two 256-wide halves of the 512 outputs ----
#pragma unroll 1
    for (int pass = 0; pass < 2; pass++) {
        gemm_tile(d_W3 + (size_t)pass * H_DIM * K_DIM, Xs, Ws, acc, tid);
#pragma unroll
        for (int i = 0; i < 2; i++)
#pragma unroll
            for (int j = 0; j < 16; j++) {
                int h = tcol + 16 * j;
                Hs[(trow * 2 + i) * XS_STRIDE + h] = acc[i][j] + b3[pass * H_DIM + h];
            }
        __syncthreads();
        // coalesced float4 store of this half
        int m = tid >> 3, q = tid & 7;
        int row = row0 + m;
        if (row < N) {
#pragma unroll
            for (int r = 0; r < 8; r++) {
                int c4 = q + 8 * r;
                float4 v4 = *reinterpret_cast<const float4*>(Hs + m * XS_STRIDE + c4 * 4);
                *reinterpret_cast<float4*>(out + (size_t)row * OUT_DIM + pass * H_DIM + c4 * 4) = v4;
            }
        }
        // pass1's first staging __syncthreads orders these Hs reads vs rewrites
    }
}

// ---------------------------------------------------------------------------
extern "C" void kernel_launch(void* const* d_in, const int* in_sizes, int n_in,
                              void* d_out, int out_size) {
    const float* x        = (const float*)d_in[0];
    const float* cond     = (const float*)d_in[1];
    const int*   batch_ids= (const int*)  d_in[2];
    const float* v_cond   = (const float*)d_in[3];
    const float* g_cond   = (const float*)d_in[4];
    const float* b_cond   = (const float*)d_in[5];
    const float* v1       = (const float*)d_in[6];
    // g1 = d_in[7]
    const float* g1       = (const float*)d_in[7];
    const float* v2       = (const float*)d_in[8];
    const float* g2       = (const float*)d_in[9];
    const float* b2       = (const float*)d_in[10];
    const float* v3       = (const float*)d_in[11];
    const float* g3       = (const float*)d_in[12];
    const float* b3       = (const float*)d_in[13];
    float* out = (float*)d_out;

    int N = in_sizes[0] / K_DIM;

    // prep: weight-norm all matrices, build FiLM tables
    wn_kernel<<<OUT_DIM, 256>>>(v_cond, g_cond, 0);
    wn_kernel<<<H_DIM,   256>>>(v1, g1, 1);
    wn_kernel<<<H_DIM,   256>>>(v2, g2, 2);
    wn_kernel<<<OUT_DIM, 256>>>(v3, g3, 3);
    film_kernel<<<G_DIM, 256>>>(cond, b_cond);

    // main fused kernel
    const int smem_bytes = (2 * TILE_M * XS_STRIDE + 256 * WS_STRIDE) * (int)sizeof(float);
    cudaFuncSetAttribute(fused_kernel, cudaFuncAttributeMaxDynamicSharedMemorySize, smem_bytes);
    int grid = (N + TILE_M - 1) / TILE_M;
    fused_kernel<<<grid, 256, smem_bytes>>>(x, batch_ids, b2, b3, out, N);
}

// round 2
// speedup vs baseline: 1.0212x; 1.0212x over previous
#include <cuda_runtime.h>
#include <math.h>

#define K_DIM 256
#define H_DIM 256
#define OUT_DIM 512
#define G_DIM 256
#define TILE_M 64
#define NTHREADS 512
#define XS_STRIDE 260   // floats per row of activation tiles
#define WST 264         // floats per k-row of transposed weight stage (264 % 32 == 8, %4 == 0)

// Device scratch (no allocations allowed)
__device__ float d_W1[H_DIM * K_DIM];
__device__ float d_W2[H_DIM * H_DIM];
__device__ float d_W3[OUT_DIM * H_DIM];
__device__ float d_Wc[OUT_DIM * K_DIM];
__device__ float d_GAMMA[G_DIM * H_DIM];
__device__ float d_BETA[G_DIM * H_DIM];

// ---------------- packed f32x2 helpers ----------------
__device__ __forceinline__ unsigned long long dup2(float a) {
    unsigned long long r;
    asm("mov.b64 %0, {%1, %1};" : "=l"(r) : "r"(__float_as_uint(a)));
    return r;
}
__device__ __forceinline__ void ffma2(unsigned long long& d,
                                      unsigned long long a,
                                      unsigned long long b) {
    asm("fma.rn.f32x2 %0, %1, %2, %0;" : "+l"(d) : "l"(a), "l"(b));
}
__device__ __forceinline__ float lo32(unsigned long long v) {
    return __uint_as_float((unsigned)v);
}
__device__ __forceinline__ float hi32(unsigned long long v) {
    return __uint_as_float((unsigned)(v >> 32));
}

// ---------------------------------------------------------------------------
// Weight normalization: W[r] = v[r] * g[r] / ||v[r]||
// ---------------------------------------------------------------------------
__global__ void wn_kernel(const float* __restrict__ v,
                          const float* __restrict__ g,
                          int which) {
    float* W = (which == 0) ? d_Wc : (which == 1) ? d_W1 : (which == 2) ? d_W2 : d_W3;
    int r = blockIdx.x, t = threadIdx.x;
    float x = v[r * K_DIM + t];
    float ss = x * x;
#pragma unroll
    for (int o = 16; o; o >>= 1) ss += __shfl_xor_sync(0xffffffffu, ss, o);
    __shared__ float red[8];
    __shared__ float s_scale;
    if ((t & 31) == 0) red[t >> 5] = ss;
    __syncthreads();
    if (t == 0) {
        float tot = 0.f;
#pragma unroll
        for (int i = 0; i < 8; i++) tot += red[i];
        s_scale = g[r] / sqrtf(tot);
    }
    __syncthreads();
    W[r * K_DIM + t] = x * s_scale;
}

// ---------------------------------------------------------------------------
// FiLM table: gamma/beta per group
// ---------------------------------------------------------------------------
__global__ void film_kernel(const float* __restrict__ cond,
                            const float* __restrict__ b_cond) {
    __shared__ float cs[K_DIM];
    int g = blockIdx.x, t = threadIdx.x;
    cs[t] = cond[g * K_DIM + t];
    __syncthreads();
    const float* w0 = d_Wc + (size_t)t * K_DIM;
    const float* w1 = d_Wc + (size_t)(t + 256) * K_DIM;
    float a0 = 0.f, a1 = 0.f;
#pragma unroll 8
    for (int k = 0; k < K_DIM; k++) {
        float c = cs[k];
        a0 = fmaf(c, w0[k], a0);
        a1 = fmaf(c, w1[k], a1);
    }
    d_GAMMA[g * H_DIM + t] = a0 + b_cond[t] + 1.0f;
    d_BETA[g * H_DIM + t]  = a1 + b_cond[t + 256];
}

// ---------------------------------------------------------------------------
// Packed-f32x2 GEMM tile: C[64 x 256] = A[64 x 256] @ Wg[256 x 256]^T
// 512 threads as 32(trow) x 16(tcol); thread owns 2 m-rows x 16 h-cols
// (cols = tcol*4 + 64*jg + {0..3}), acc packed as 8 f32x2 pairs per row.
// Weights staged TRANSPOSED into Ws[k][h] with h XOR (k & 28) swizzle:
// conflict-free transposing stores and conflict-free float4 loads.
// ---------------------------------------------------------------------------
__device__ __forceinline__ void gemm_tile(const float* __restrict__ Wg,
                                          const float* __restrict__ A,
                                          float* __restrict__ Ws,
                                          unsigned long long acc[2][8],
                                          int tid) {
    const int trow = tid >> 4, tcol = tid & 15;
    const int lh = tid >> 3, lq = tid & 7;
#pragma unroll
    for (int i = 0; i < 2; i++)
#pragma unroll
        for (int j = 0; j < 8; j++) acc[i][j] = 0ull;

    const float* a0base = A + (trow * 2 + 0) * XS_STRIDE;
    const float* a1base = A + (trow * 2 + 1) * XS_STRIDE;

#pragma unroll 1
    for (int k0 = 0; k0 < K_DIM; k0 += 32) {
        __syncthreads();  // protect Ws from previous chunk/phase
        // stage 32-wide k-chunk, transposed + swizzled
#pragma unroll
        for (int r = 0; r < 4; r++) {
            int hh = lh + 64 * r;
            float4 w4 = *reinterpret_cast<const float4*>(Wg + (size_t)hh * K_DIM + k0 + lq * 4);
            int phys = hh ^ (lq * 4);           // xor(kk) = kk & 28 = 4*lq for e=0..3
            Ws[(lq * 4 + 0) * WST + phys] = w4.x;
            Ws[(lq * 4 + 1) * WST + phys] = w4.y;
            Ws[(lq * 4 + 2) * WST + phys] = w4.z;
            Ws[(lq * 4 + 3) * WST + phys] = w4.w;
        }
        __syncthreads();

#pragma unroll
        for (int kb = 0; kb < 32; kb += 4) {
            float4 a0 = *reinterpret_cast<const float4*>(a0base + k0 + kb);
            float4 a1 = *reinterpret_cast<const float4*>(a1base + k0 + kb);
            const int cb = (tcol * 4) ^ kb;      // kb == kk & 28 inside this group
            const float a0e[4] = {a0.x, a0.y, a0.z, a0.w};
            const float a1e[4] = {a1.x, a1.y, a1.z, a1.w};
#pragma unroll
            for (int e = 0; e < 4; e++) {
                const int kk = kb + e;
                unsigned long long av0 = dup2(a0e[e]);
                unsigned long long av1 = dup2(a1e[e]);
                const float* wrow = Ws + kk * WST + cb;
#pragma unroll
                for (int jg = 0; jg < 4; jg++) {
                    ulonglong2 b2v = *reinterpret_cast<const ulonglong2*>(wrow + 64 * jg);
                    ffma2(acc[0][jg * 2 + 0], av0, b2v.x);
                    ffma2(acc[0][jg * 2 + 1], av0, b2v.y);
                    ffma2(acc[1][jg * 2 + 0], av1, b2v.x);
                    ffma2(acc[1][jg * 2 + 1], av1, b2v.y);
                }
            }
        }
    }
}

// ---------------------------------------------------------------------------
// Fused main kernel
// ---------------------------------------------------------------------------
__global__ void __launch_bounds__(NTHREADS, 1)
fused_kernel(const float* __restrict__ x,
             const int* __restrict__ batch_ids,
             const float* __restrict__ b2,
             const float* __restrict__ b3,
             float* __restrict__ out, int N) {
    extern __shared__ float smem[];
    float* Xs = smem;                            // TILE_M * XS_STRIDE
    float* Hs = smem + TILE_M * XS_STRIDE;       // TILE_M * XS_STRIDE
    float* Ws = Hs + TILE_M * XS_STRIDE;         // 32 * WST

    const int tid = threadIdx.x;
    const int row0 = blockIdx.x * TILE_M;
    const int trow = tid >> 4, tcol = tid & 15;

    // cooperative X-tile load (float4, coalesced): 64 rows x 64 float4
    {
        int m = tid >> 3, q = tid & 7;
        int row = row0 + m;
        const float4 z4 = make_float4(0.f, 0.f, 0.f, 0.f);
#pragma unroll
        for (int r = 0; r < 8; r++) {
            int c4 = q + 8 * r;
            float4 v4 = (row < N)
                ? *reinterpret_cast<const float4*>(x + (size_t)row * K_DIM + c4 * 4)
                : z4;
            *reinterpret_cast<float4*>(Xs + m * XS_STRIDE + c4 * 4) = v4;
        }
    }
    __syncthreads();

    unsigned long long acc[2][8];

    // ---- GEMM1: Hs_pre = Xs @ W1^T ----
    gemm_tile(d_W1, Xs, Ws, acc, tid);
#pragma unroll
    for (int i = 0; i < 2; i++)
#pragma unroll
        for (int jg = 0; jg < 4; jg++) {
            int h = tcol * 4 + 64 * jg;
            float* dst = Hs + (trow * 2 + i) * XS_STRIDE + h;
            *reinterpret_cast<unsigned long long*>(dst + 0) = acc[i][jg * 2 + 0];
            *reinterpret_cast<unsigned long long*>(dst + 2) = acc[i][jg * 2 + 1];
        }
    __syncthreads();

    // ---- layernorm + FiLM + relu in place on Hs; warp w -> rows 4w..4w+3 ----
    {
        int w = tid >> 5, l = tid & 31;
#pragma unroll
        for (int mm = 0; mm < 4; mm++) {
            int m = w * 4 + mm;
            float v[8];
            float s = 0.f, ss = 0.f;
#pragma unroll
            for (int p = 0; p < 8; p++) {
                v[p] = Hs[m * XS_STRIDE + l + 32 * p];
                s += v[p];
                ss = fmaf(v[p], v[p], ss);
            }
#pragma unroll
            for (int o = 16; o; o >>= 1) {
                s  += __shfl_xor_sync(0xffffffffu, s, o);
                ss += __shfl_xor_sync(0xffffffffu, ss, o);
            }
            float mu   = s * (1.f / 256.f);
            float var  = ss * (1.f / 256.f) - mu * mu;
            float rstd = rsqrtf(var + 1e-5f);
            int row = row0 + m;
            int bid = (row < N) ? batch_ids[row] : 0;
            const float* gp = d_GAMMA + (size_t)bid * H_DIM;
            const float* bp = d_BETA  + (size_t)bid * H_DIM;
#pragma unroll
            for (int p = 0; p < 8; p++) {
                int h = l + 32 * p;
                float t2 = fmaf((v[p] - mu) * rstd, gp[h], bp[h]);
                Hs[m * XS_STRIDE + h] = fmaxf(t2, 0.f);
            }
        }
    }
    // gemm_tile's leading __syncthreads orders Hs writes before reads

    // ---- GEMM2: Xs = relu(Hs @ W2^T + b2) ----
    gemm_tile(d_W2, Hs, Ws, acc, tid);
#pragma unroll
    for (int i = 0; i < 2; i++)
#pragma unroll
        for (int jg = 0; jg < 4; jg++) {
            int h = tcol * 4 + 64 * jg;
            float* dst = Xs + (trow * 2 + i) * XS_STRIDE + h;
#pragma unroll
            for (int p = 0; p < 2; p++) {
                unsigned long long a = acc[i][jg * 2 + p];
                float2 o2;
                o2.x = fmaxf(lo32(a) + b2[h + 2 * p + 0], 0.f);
                o2.y = fmaxf(hi32(a) + b2[h + 2 * p + 1], 0.f);
                *reinterpret_cast<float2*>(dst + 2 * p) = o2;
            }
        }

    // ---- GEMM3: two 256-wide halves of the 512 outputs ----
#pragma unroll 1
    for (int pass = 0; pass < 2; pass++) {
        gemm_tile(d_W3 + (size_t)pass * H_DIM * K_DIM, Xs, Ws, acc, tid);
#pragma unroll
        for (int i = 0; i < 2; i++)
#pragma unroll
            for (int jg = 0; jg < 4; jg++) {
                int h = tcol * 4 + 64 * jg;
                float* dst = Hs + (trow * 2 + i) * XS_STRIDE + h;
#pragma unroll
                for (int p = 0; p < 2; p++) {
                    unsigned long long a = acc[i][jg * 2 + p];
                    float2 o2;
                    o2.x = lo32(a) + b3[pass * H_DIM + h + 2 * p + 0];
                    o2.y = hi32(a) + b3[pass * H_DIM + h + 2 * p + 1];
                    *reinterpret_cast<float2*>(dst + 2 * p) = o2;
                }
            }
        __syncthreads();
        // coalesced float4 store of this half: 64 rows x 64 float4
        int m = tid >> 3, q = tid & 7;
        int row = row0 + m;
        if (row < N) {
#pragma unroll
            for (int r = 0; r < 8; r++) {
                int c4 = q + 8 * r;
                float4 v4 = *reinterpret_cast<const float4*>(Hs + m * XS_STRIDE + c4 * 4);
                *reinterpret_cast<float4*>(out + (size_t)row * OUT_DIM + pass * H_DIM + c4 * 4) = v4;
            }
        }
        // next gemm_tile's first __syncthreads orders these Hs reads vs rewrites
    }
}

// ---------------------------------------------------------------------------
extern "C" void kernel_launch(void* const* d_in, const int* in_sizes, int n_in,
                              void* d_out, int out_size) {
    const float* x        = (const float*)d_in[0];
    const float* cond     = (const float*)d_in[1];
    const int*   batch_ids= (const int*)  d_in[2];
    const float* v_cond   = (const float*)d_in[3];
    const float* g_cond   = (const float*)d_in[4];
    const float* b_cond   = (const float*)d_in[5];
    const float* v1       = (const float*)d_in[6];
    const float* g1       = (const float*)d_in[7];
    const float* v2       = (const float*)d_in[8];
    const float* g2       = (const float*)d_in[9];
    const float* b2       = (const float*)d_in[10];
    const float* v3       = (const float*)d_in[11];
    const float* g3       = (const float*)d_in[12];
    const float* b3       = (const float*)d_in[13];
    float* out = (float*)d_out;

    int N = in_sizes[0] / K_DIM;

    wn_kernel<<<OUT_DIM, 256>>>(v_cond, g_cond, 0);
    wn_kernel<<<H_DIM,   256>>>(v1, g1, 1);
    wn_kernel<<<H_DIM,   256>>>(v2, g2, 2);
    wn_kernel<<<OUT_DIM, 256>>>(v3, g3, 3);
    film_kernel<<<G_DIM, 256>>>(cond, b_cond);

    const int smem_bytes = (2 * TILE_M * XS_STRIDE + 32 * WST) * (int)sizeof(float);
    cudaFuncSetAttribute(fused_kernel, cudaFuncAttributeMaxDynamicSharedMemorySize, smem_bytes);
    int grid = (N + TILE_M - 1) / TILE_M;
    fused_kernel<<<grid, NTHREADS, smem_bytes>>>(x, batch_ids, b2, b3, out, N);
}

// round 5
// speedup vs baseline: 2.8461x; 2.7869x over previous
#include <cuda_runtime.h>
#include <cuda_bf16.h>
#include <math.h>
#include <stdint.h>

#define K_DIM 256
#define H_DIM 256
#define OUT_DIM 512
#define G_DIM 256
#define TILE_M 128
#define NTH 512

// ---- smem layout (bytes) ----
#define ASTR_B 528            // 264 bf16 per A row
#define WSTR_B 80             // 40 bf16 per W row (32 real k + pad)
#define A_HI 0
#define A_LO 67584            // 128*528
#define WBUF 135168           // 2 bufs x 2 comps x 20480
#define WBUF_SZ 20480         // 256*80
#define PART 217088           // 128 rows x 4 warps x float2
#define STAT 221184           // 128 x float2 (mu, rstd)
#define SBID 222208           // 128 x int
#define SMEM_TOTAL 222720

// ---------------- global scratch ----------------
__device__ float d_Wc[OUT_DIM * K_DIM];
__device__ float d_GAMMA[G_DIM * H_DIM];
__device__ float d_BETA[G_DIM * H_DIM];
__device__ __nv_bfloat16 d_W1h[H_DIM * K_DIM], d_W1l[H_DIM * K_DIM];
__device__ __nv_bfloat16 d_W2h[H_DIM * K_DIM], d_W2l[H_DIM * K_DIM];
__device__ __nv_bfloat16 d_W3h[OUT_DIM * K_DIM], d_W3l[OUT_DIM * K_DIM];

// ---------------- asm helpers ----------------
__device__ __forceinline__ uint32_t smem_u32(const void* p) {
    uint32_t a;
    asm("{ .reg .u64 t; cvta.to.shared.u64 t, %1; cvt.u32.u64 %0, t; }" : "=r"(a) : "l"(p));
    return a;
}
__device__ __forceinline__ void ldsm4(uint32_t (&r)[4], uint32_t a) {
    asm volatile("ldmatrix.sync.aligned.m8n8.x4.shared.b16 {%0,%1,%2,%3}, [%4];"
                 : "=r"(r[0]), "=r"(r[1]), "=r"(r[2]), "=r"(r[3]) : "r"(a));
}
__device__ __forceinline__ void mma16816(float* c, const uint32_t* a, uint32_t b0, uint32_t b1) {
    asm volatile("mma.sync.aligned.m16n8k16.row.col.f32.bf16.bf16.f32 "
                 "{%0,%1,%2,%3}, {%4,%5,%6,%7}, {%8,%9}, {%0,%1,%2,%3};"
                 : "+f"(c[0]), "+f"(c[1]), "+f"(c[2]), "+f"(c[3])
                 : "r"(a[0]), "r"(a[1]), "r"(a[2]), "r"(a[3]), "r"(b0), "r"(b1));
}
__device__ __forceinline__ void cp16(uint32_t dst, const void* src) {
    asm volatile("cp.async.cg.shared.global [%0], [%1], 16;" :: "r"(dst), "l"(src) : "memory");
}
#define CP_COMMIT() asm volatile("cp.async.commit_group;" ::: "memory")
#define CP_WAIT1()  asm volatile("cp.async.wait_group 1;" ::: "memory")
#define CP_WAIT0()  asm volatile("cp.async.wait_group 0;" ::: "memory")

// ---------------------------------------------------------------------------
// prep kernels
// ---------------------------------------------------------------------------
__global__ void wn_kernel(const float* __restrict__ v, const float* __restrict__ g, int which) {
    int r = blockIdx.x, t = threadIdx.x;
    float x = v[r * K_DIM + t];
    float ss = x * x;
#pragma unroll
    for (int o = 16; o; o >>= 1) ss += __shfl_xor_sync(0xffffffffu, ss, o);
    __shared__ float red[8];
    __shared__ float s_scale;
    if ((t & 31) == 0) red[t >> 5] = ss;
    __syncthreads();
    if (t == 0) {
        float tot = 0.f;
#pragma unroll
        for (int i = 0; i < 8; i++) tot += red[i];
        s_scale = g[r] / sqrtf(tot);
    }
    __syncthreads();
    float wv = x * s_scale;
    if (which == 0) { d_Wc[r * K_DIM + t] = wv; return; }
    __nv_bfloat16* Wh = (which == 1) ? d_W1h : (which == 2) ? d_W2h : d_W3h;
    __nv_bfloat16* Wl = (which == 1) ? d_W1l : (which == 2) ? d_W2l : d_W3l;
    __nv_bfloat16 hi = __float2bfloat16(wv);
    __nv_bfloat16 lo = __float2bfloat16(wv - __bfloat162float(hi));
    Wh[r * K_DIM + t] = hi;
    Wl[r * K_DIM + t] = lo;
}

__global__ void film_kernel(const float* __restrict__ cond, const float* __restrict__ b_cond) {
    __shared__ float cs[K_DIM];
    int g = blockIdx.x, t = threadIdx.x;
    cs[t] = cond[g * K_DIM + t];
    __syncthreads();
    const float* w0 = d_Wc + (size_t)t * K_DIM;
    const float* w1 = d_Wc + (size_t)(t + 256) * K_DIM;
    float a0 = 0.f, a1 = 0.f;
#pragma unroll 8
    for (int k = 0; k < K_DIM; k++) {
        float c = cs[k];
        a0 = fmaf(c, w0[k], a0);
        a1 = fmaf(c, w1[k], a1);
    }
    d_GAMMA[g * H_DIM + t] = a0 + b_cond[t] + 1.0f;
    d_BETA[g * H_DIM + t]  = a1 + b_cond[t + 256];
}

// ---------------------------------------------------------------------------
// stage one 32-wide k chunk of W (hi+lo) into buffer `buf` via cp.async
// ---------------------------------------------------------------------------
__device__ __forceinline__ void stage_chunk(uint32_t sb,
                                            const char* Wh, const char* Wl,
                                            int ck, int buf, int tid) {
#pragma unroll
    for (int i = 0; i < 4; i++) {
        int u = tid + NTH * i;              // 0..2047 16B granules
        int comp = u >> 10;                  // 0=hi 1=lo
        int rr = (u >> 2) & 255;             // n row
        int q = u & 3;                       // 16B quad within 64B chunk
        const char* src = (comp ? Wl : Wh) + (size_t)rr * (K_DIM * 2) + ck * 64 + q * 16;
        uint32_t dst = sb + WBUF + buf * (2 * WBUF_SZ) + comp * WBUF_SZ + rr * WSTR_B + q * 16;
        cp16(dst, src);
    }
    CP_COMMIT();
}

// ---------------------------------------------------------------------------
// compute one 32-wide k chunk with 3-term bf16-split MMAs
// W fragments: non-trans ldmatrix (W is [n][k] = col-major B for row.col mma)
// ---------------------------------------------------------------------------
__device__ __forceinline__ void compute_chunk(uint32_t sb, int buf, int ck,
                                              float (&acc)[2][8][4],
                                              int m0, int n0, int lane) {
    const uint32_t arow = m0 + (lane & 15);
    const uint32_t koff = (lane >> 4) * 8;
    const uint32_t nrow = n0 + (lane & 15);
    const uint32_t wbase = sb + WBUF + buf * (2 * WBUF_SZ);
#pragma unroll
    for (int s = 0; s < 32; s += 16) {
        const int kg = ck * 32 + s;
        uint32_t ah0[4], ah1[4], al0[4], al1[4];
        uint32_t aoff = arow * ASTR_B + (kg + koff) * 2;
        ldsm4(ah0, sb + A_HI + aoff);
        ldsm4(ah1, sb + A_HI + aoff + 16 * ASTR_B);
        ldsm4(al0, sb + A_LO + aoff);
        ldsm4(al1, sb + A_LO + aoff + 16 * ASTR_B);

        uint32_t woff = nrow * WSTR_B + (s + koff) * 2;
        uint32_t wf[4][4];
#pragma unroll
        for (int g = 0; g < 4; g++) ldsm4(wf[g], wbase + woff + g * 16 * WSTR_B);
#pragma unroll
        for (int g = 0; g < 4; g++) {
            mma16816(acc[0][2 * g + 0], ah0, wf[g][0], wf[g][2]);
            mma16816(acc[0][2 * g + 1], ah0, wf[g][1], wf[g][3]);
            mma16816(acc[1][2 * g + 0], ah1, wf[g][0], wf[g][2]);
            mma16816(acc[1][2 * g + 1], ah1, wf[g][1], wf[g][3]);
            mma16816(acc[0][2 * g + 0], al0, wf[g][0], wf[g][2]);
            mma16816(acc[0][2 * g + 1], al0, wf[g][1], wf[g][3]);
            mma16816(acc[1][2 * g + 0], al1, wf[g][0], wf[g][2]);
            mma16816(acc[1][2 * g + 1], al1, wf[g][1], wf[g][3]);
        }
#pragma unroll
        for (int g = 0; g < 4; g++) ldsm4(wf[g], wbase + WBUF_SZ + woff + g * 16 * WSTR_B);
#pragma unroll
        for (int g = 0; g < 4; g++) {
            mma16816(acc[0][2 * g + 0], ah0, wf[g][0], wf[g][2]);
            mma16816(acc[0][2 * g + 1], ah0, wf[g][1], wf[g][3]);
            mma16816(acc[1][2 * g + 0], ah1, wf[g][0], wf[g][2]);
            mma16816(acc[1][2 * g + 1], ah1, wf[g][1], wf[g][3]);
        }
    }
}

// full GEMM: acc[128x256] = A @ W^T (3-term split), W double-buffered
__device__ __forceinline__ void gemm_mma(uint32_t sb,
                                         const __nv_bfloat16* Wh, const __nv_bfloat16* Wl,
                                         float (&acc)[2][8][4],
                                         int m0, int n0, int lane, int tid) {
#pragma unroll
    for (int i = 0; i < 2; i++)
#pragma unroll
        for (int j = 0; j < 8; j++)
#pragma unroll
            for (int q = 0; q < 4; q++) acc[i][j][q] = 0.f;

    stage_chunk(sb, (const char*)Wh, (const char*)Wl, 0, 0, tid);
#pragma unroll 1
    for (int ck = 0; ck < 8; ck++) {
        if (ck < 7) {
            stage_chunk(sb, (const char*)Wh, (const char*)Wl, ck + 1, (ck + 1) & 1, tid);
            CP_WAIT1();
        } else {
            CP_WAIT0();
        }
        __syncthreads();
        compute_chunk(sb, ck & 1, ck, acc, m0, n0, lane);
        __syncthreads();
    }
}

// split fp32 pair -> bf16 hi/lo and store into A buffers at (row, k)
__device__ __forceinline__ void sts_split2(char* smem, int row, int k, float y0, float y1) {
    __nv_bfloat16 h0 = __float2bfloat16(y0);
    __nv_bfloat16 l0 = __float2bfloat16(y0 - __bfloat162float(h0));
    __nv_bfloat16 h1 = __float2bfloat16(y1);
    __nv_bfloat16 l1 = __float2bfloat16(y1 - __bfloat162float(h1));
    uint32_t off = row * ASTR_B + k * 2;
    *reinterpret_cast<__nv_bfloat162*>(smem + A_HI + off) = __halves2bfloat162(h0, h1);
    *reinterpret_cast<__nv_bfloat162*>(smem + A_LO + off) = __halves2bfloat162(l0, l1);
}

// ---------------------------------------------------------------------------
__global__ void __launch_bounds__(NTH, 1)
fused_mma(const float* __restrict__ x,
          const int* __restrict__ bids,
          const float* __restrict__ b2,
          const float* __restrict__ b3,
          float* __restrict__ out, int N) {
    extern __shared__ __align__(16) char smem[];
    const uint32_t sb = smem_u32(smem);
    const int tid = threadIdx.x;
    const int lane = tid & 31, w = tid >> 5;
    const int warp_m = w >> 2, warp_n = w & 3;
    const int m0 = warp_m * 32, n0 = warp_n * 64;
    const int lgrp = lane >> 2, lq = lane & 3;
    const int row0 = blockIdx.x * TILE_M;

    // ---- build A (hi/lo bf16) from x tile [128 x 256] ----
#pragma unroll 4
    for (int i = 0; i < 16; i++) {
        int idx = tid + NTH * i;            // 8192 float4 groups
        int m = idx >> 6, c4 = idx & 63;
        int row = row0 + m;
        float4 v = (row < N) ? reinterpret_cast<const float4*>(x)[(size_t)row * 64 + c4]
                             : make_float4(0.f, 0.f, 0.f, 0.f);
        sts_split2(smem, m, c4 * 4 + 0, v.x, v.y);
        sts_split2(smem, m, c4 * 4 + 2, v.z, v.w);
    }

    float acc[2][8][4];

    // ================= GEMM1 + layernorm/FiLM/relu =================
    gemm_mma(sb, d_W1h, d_W1l, acc, m0, n0, lane, tid);
    {
        // per-row partial sums
#pragma unroll
        for (int mi = 0; mi < 2; mi++)
#pragma unroll
            for (int half = 0; half < 2; half++) {
                float s = 0.f, ss = 0.f;
#pragma unroll
                for (int j = 0; j < 8; j++) {
                    float v0 = acc[mi][j][half * 2 + 0];
                    float v1 = acc[mi][j][half * 2 + 1];
                    s += v0 + v1;
                    ss = fmaf(v0, v0, fmaf(v1, v1, ss));
                }
                s  += __shfl_xor_sync(0xffffffffu, s, 1);
                s  += __shfl_xor_sync(0xffffffffu, s, 2);
                ss += __shfl_xor_sync(0xffffffffu, ss, 1);
                ss += __shfl_xor_sync(0xffffffffu, ss, 2);
                if (lq == 0) {
                    int r = m0 + mi * 16 + half * 8 + lgrp;
                    *reinterpret_cast<float2*>(smem + PART + (r * 4 + warp_n) * 8) =
                        make_float2(s, ss);
                }
            }
        __syncthreads();
        if (tid < 128) {
            float s = 0.f, ss = 0.f;
#pragma unroll
            for (int q = 0; q < 4; q++) {
                float2 p = *reinterpret_cast<float2*>(smem + PART + (tid * 4 + q) * 8);
                s += p.x;
                ss += p.y;
            }
            float mu = s * (1.f / 256.f);
            float var = ss * (1.f / 256.f) - mu * mu;
            float rstd = rsqrtf(var + 1e-5f);
            *reinterpret_cast<float2*>(smem + STAT + tid * 8) = make_float2(mu, rstd);
            int row = row0 + tid;
            *reinterpret_cast<int*>(smem + SBID + tid * 4) = (row < N) ? bids[row] : 0;
        }
        __syncthreads();
        // apply: y = relu(gamma*(v-mu)*rstd + beta), write bf16 split to A
#pragma unroll
        for (int mi = 0; mi < 2; mi++)
#pragma unroll
            for (int half = 0; half < 2; half++) {
                int r = m0 + mi * 16 + half * 8 + lgrp;
                float2 st = *reinterpret_cast<float2*>(smem + STAT + r * 8);
                int bid = *reinterpret_cast<int*>(smem + SBID + r * 4);
                const float* gp = d_GAMMA + (size_t)bid * H_DIM;
                const float* bp = d_BETA  + (size_t)bid * H_DIM;
#pragma unroll
                for (int j = 0; j < 8; j++) {
                    int c = n0 + j * 8 + lq * 2;
                    float2 g2 = *reinterpret_cast<const float2*>(gp + c);
                    float2 be = *reinterpret_cast<const float2*>(bp + c);
                    float y0 = fmaxf(fmaf((acc[mi][j][half * 2 + 0] - st.x) * st.y, g2.x, be.x), 0.f);
                    float y1 = fmaxf(fmaf((acc[mi][j][half * 2 + 1] - st.x) * st.y, g2.y, be.y), 0.f);
                    sts_split2(smem, r, c, y0, y1);
                }
            }
    }

    // ================= GEMM2 + relu + b2 =================
    gemm_mma(sb, d_W2h, d_W2l, acc, m0, n0, lane, tid);
    {
        __syncthreads();  // all MMAs done before overwriting A
#pragma unroll
        for (int mi = 0; mi < 2; mi++)
#pragma unroll
            for (int half = 0; half < 2; half++) {
                int r = m0 + mi * 16 + half * 8 + lgrp;
#pragma unroll
                for (int j = 0; j < 8; j++) {
                    int c = n0 + j * 8 + lq * 2;
                    float2 bb = *reinterpret_cast<const float2*>(b2 + c);
                    float y0 = fmaxf(acc[mi][j][half * 2 + 0] + bb.x, 0.f);
                    float y1 = fmaxf(acc[mi][j][half * 2 + 1] + bb.y, 0.f);
                    sts_split2(smem, r, c, y0, y1);
                }
            }
    }

    // ================= GEMM3 (two 256-col halves) + b3 -> out =================
#pragma unroll 1
    for (int hf = 0; hf < 2; hf++) {
        gemm_mma(sb, d_W3h + (size_t)hf * 256 * K_DIM, d_W3l + (size_t)hf * 256 * K_DIM,
                 acc, m0, n0, lane, tid);
#pragma unroll
        for (int mi = 0; mi < 2; mi++)
#pragma unroll
            for (int half = 0; half < 2; half++) {
                int r = m0 + mi * 16 + half * 8 + lgrp;
                int row = row0 + r;
                if (row < N) {
                    float* op = out + (size_t)row * OUT_DIM + hf * 256;
#pragma unroll
                    for (int j = 0; j < 8; j++) {
                        int c = n0 + j * 8 + lq * 2;
                        float2 bb = *reinterpret_cast<const float2*>(b3 + hf * 256 + c);
                        float2 o2;
                        o2.x = acc[mi][j][half * 2 + 0] + bb.x;
                        o2.y = acc[mi][j][half * 2 + 1] + bb.y;
                        *reinterpret_cast<float2*>(op + c) = o2;
                    }
                }
            }
    }
}

// ---------------------------------------------------------------------------
extern "C" void kernel_launch(void* const* d_in, const int* in_sizes, int n_in,
                              void* d_out, int out_size) {
    const float* x         = (const float*)d_in[0];
    const float* cond      = (const float*)d_in[1];
    const int*   batch_ids = (const int*)  d_in[2];
    const float* v_cond    = (const float*)d_in[3];
    const float* g_cond    = (const float*)d_in[4];
    const float* b_cond    = (const float*)d_in[5];
    const float* v1        = (const float*)d_in[6];
    const float* g1        = (const float*)d_in[7];
    const float* v2        = (const float*)d_in[8];
    const float* g2        = (const float*)d_in[9];
    const float* b2        = (const float*)d_in[10];
    const float* v3        = (const float*)d_in[11];
    const float* g3        = (const float*)d_in[12];
    const float* b3        = (const float*)d_in[13];
    float* out = (float*)d_out;

    int N = in_sizes[0] / K_DIM;

    wn_kernel<<<OUT_DIM, 256>>>(v_cond, g_cond, 0);
    wn_kernel<<<H_DIM,   256>>>(v1, g1, 1);
    wn_kernel<<<H_DIM,   256>>>(v2, g2, 2);
    wn_kernel<<<OUT_DIM, 256>>>(v3, g3, 3);
    film_kernel<<<G_DIM, 256>>>(cond, b_cond);

    cudaFuncSetAttribute(fused_mma, cudaFuncAttributeMaxDynamicSharedMemorySize, SMEM_TOTAL);
    int grid = (N + TILE_M - 1) / TILE_M;
    fused_mma<<<grid, NTH, SMEM_TOTAL>>>(x, batch_ids, b2, b3, out, N);
}

// round 6
// speedup vs baseline: 2.8503x; 1.0015x over previous
#include <cuda_runtime.h>
#include <cuda_bf16.h>
#include <math.h>
#include <stdint.h>

#define K_DIM 256
#define H_DIM 256
#define OUT_DIM 512
#define G_DIM 256
#define TILE_M 128
#define NTH 512

// ---- smem layout (bytes) ----
#define ASTR_B 528            // 264 bf16 per A row
#define WSTR_B 80             // 40 bf16 per W row (32 real k + pad)
#define A_HI 0
#define A_LO 67584            // 128*528
#define WBUF 135168           // 2 bufs x 2 comps x 20480
#define WBUF_SZ 20480         // 256*80
#define PART 217088           // 128 rows x 4 warps x float2
#define STAT 221184           // 128 x float2 (mu, rstd)
#define SBID 222208           // 128 x int
#define SMEM_TOTAL 222720

// ---------------- global scratch ----------------
__device__ float d_Wc[OUT_DIM * K_DIM];
__device__ float d_GAMMA[G_DIM * H_DIM];
__device__ float d_BETA[G_DIM * H_DIM];
__device__ __nv_bfloat16 d_W1h[H_DIM * K_DIM], d_W1l[H_DIM * K_DIM];
__device__ __nv_bfloat16 d_W2h[H_DIM * K_DIM], d_W2l[H_DIM * K_DIM];
__device__ __nv_bfloat16 d_W3h[OUT_DIM * K_DIM], d_W3l[OUT_DIM * K_DIM];

// ---------------- asm helpers ----------------
__device__ __forceinline__ uint32_t smem_u32(const void* p) {
    uint32_t a;
    asm("{ .reg .u64 t; cvta.to.shared.u64 t, %1; cvt.u32.u64 %0, t; }" : "=r"(a) : "l"(p));
    return a;
}
__device__ __forceinline__ void ldsm4(uint32_t (&r)[4], uint32_t a) {
    asm volatile("ldmatrix.sync.aligned.m8n8.x4.shared.b16 {%0,%1,%2,%3}, [%4];"
                 : "=r"(r[0]), "=r"(r[1]), "=r"(r[2]), "=r"(r[3]) : "r"(a));
}
__device__ __forceinline__ void mma16816(float* c, const uint32_t* a, uint32_t b0, uint32_t b1) {
    asm volatile("mma.sync.aligned.m16n8k16.row.col.f32.bf16.bf16.f32 "
                 "{%0,%1,%2,%3}, {%4,%5,%6,%7}, {%8,%9}, {%0,%1,%2,%3};"
                 : "+f"(c[0]), "+f"(c[1]), "+f"(c[2]), "+f"(c[3])
                 : "r"(a[0]), "r"(a[1]), "r"(a[2]), "r"(a[3]), "r"(b0), "r"(b1));
}
__device__ __forceinline__ void cp16(uint32_t dst, const void* src) {
    asm volatile("cp.async.cg.shared.global [%0], [%1], 16;" :: "r"(dst), "l"(src) : "memory");
}
#define CP_COMMIT() asm volatile("cp.async.commit_group;" ::: "memory")
#define CP_WAIT1()  asm volatile("cp.async.wait_group 1;" ::: "memory")
#define CP_WAIT0()  asm volatile("cp.async.wait_group 0;" ::: "memory")

// ---------------------------------------------------------------------------
// prep kernels
// ---------------------------------------------------------------------------
__global__ void wn_kernel(const float* __restrict__ v, const float* __restrict__ g, int which) {
    int r = blockIdx.x, t = threadIdx.x;
    float x = v[r * K_DIM + t];
    float ss = x * x;
#pragma unroll
    for (int o = 16; o; o >>= 1) ss += __shfl_xor_sync(0xffffffffu, ss, o);
    __shared__ float red[8];
    __shared__ float s_scale;
    if ((t & 31) == 0) red[t >> 5] = ss;
    __syncthreads();
    if (t == 0) {
        float tot = 0.f;
#pragma unroll
        for (int i = 0; i < 8; i++) tot += red[i];
        s_scale = g[r] / sqrtf(tot);
    }
    __syncthreads();
    float wv = x * s_scale;
    if (which == 0) { d_Wc[r * K_DIM + t] = wv; return; }
    __nv_bfloat16* Wh = (which == 1) ? d_W1h : (which == 2) ? d_W2h : d_W3h;
    __nv_bfloat16* Wl = (which == 1) ? d_W1l : (which == 2) ? d_W2l : d_W3l;
    __nv_bfloat16 hi = __float2bfloat16(wv);
    __nv_bfloat16 lo = __float2bfloat16(wv - __bfloat162float(hi));
    Wh[r * K_DIM + t] = hi;
    Wl[r * K_DIM + t] = lo;
}

__global__ void film_kernel(const float* __restrict__ cond, const float* __restrict__ b_cond) {
    __shared__ float cs[K_DIM];
    int g = blockIdx.x, t = threadIdx.x;
    cs[t] = cond[g * K_DIM + t];
    __syncthreads();
    const float* w0 = d_Wc + (size_t)t * K_DIM;
    const float* w1 = d_Wc + (size_t)(t + 256) * K_DIM;
    float a0 = 0.f, a1 = 0.f;
#pragma unroll 8
    for (int k = 0; k < K_DIM; k++) {
        float c = cs[k];
        a0 = fmaf(c, w0[k], a0);
        a1 = fmaf(c, w1[k], a1);
    }
    d_GAMMA[g * H_DIM + t] = a0 + b_cond[t] + 1.0f;
    d_BETA[g * H_DIM + t]  = a1 + b_cond[t + 256];
}

// ---------------------------------------------------------------------------
// stage one 32-wide k chunk of W (hi+lo) into buffer `buf` via cp.async
// ---------------------------------------------------------------------------
__device__ __forceinline__ void stage_chunk(uint32_t sb,
                                            const char* Wh, const char* Wl,
                                            int ck, int buf, int tid) {
#pragma unroll
    for (int i = 0; i < 4; i++) {
        int u = tid + NTH * i;              // 0..2047 16B granules
        int comp = u >> 10;                  // 0=hi 1=lo
        int rr = (u >> 2) & 255;             // n row
        int q = u & 3;                       // 16B quad within 64B chunk
        const char* src = (comp ? Wl : Wh) + (size_t)rr * (K_DIM * 2) + ck * 64 + q * 16;
        uint32_t dst = sb + WBUF + buf * (2 * WBUF_SZ) + comp * WBUF_SZ + rr * WSTR_B + q * 16;
        cp16(dst, src);
    }
    CP_COMMIT();
}

// ---------------------------------------------------------------------------
// compute one 32-wide k chunk with 3-term bf16-split MMAs
// W fragments: non-trans ldmatrix (W is [n][k] = col-major B for row.col mma)
// ---------------------------------------------------------------------------
__device__ __forceinline__ void compute_chunk(uint32_t sb, int buf, int ck,
                                              float (&acc)[2][8][4],
                                              int m0, int n0, int lane) {
    const uint32_t arow = m0 + (lane & 15);
    const uint32_t koff = (lane >> 4) * 8;
    const uint32_t nrow = n0 + (lane & 15);
    const uint32_t wbase = sb + WBUF + buf * (2 * WBUF_SZ);
#pragma unroll
    for (int s = 0; s < 32; s += 16) {
        const int kg = ck * 32 + s;
        uint32_t ah0[4], ah1[4], al0[4], al1[4];
        uint32_t aoff = arow * ASTR_B + (kg + koff) * 2;
        ldsm4(ah0, sb + A_HI + aoff);
        ldsm4(ah1, sb + A_HI + aoff + 16 * ASTR_B);
        ldsm4(al0, sb + A_LO + aoff);
        ldsm4(al1, sb + A_LO + aoff + 16 * ASTR_B);

        uint32_t woff = nrow * WSTR_B + (s + koff) * 2;
        uint32_t wf[4][4];
#pragma unroll
        for (int g = 0; g < 4; g++) ldsm4(wf[g], wbase + woff + g * 16 * WSTR_B);
#pragma unroll
        for (int g = 0; g < 4; g++) {
            mma16816(acc[0][2 * g + 0], ah0, wf[g][0], wf[g][2]);
            mma16816(acc[0][2 * g + 1], ah0, wf[g][1], wf[g][3]);
            mma16816(acc[1][2 * g + 0], ah1, wf[g][0], wf[g][2]);
            mma16816(acc[1][2 * g + 1], ah1, wf[g][1], wf[g][3]);
            mma16816(acc[0][2 * g + 0], al0, wf[g][0], wf[g][2]);
            mma16816(acc[0][2 * g + 1], al0, wf[g][1], wf[g][3]);
            mma16816(acc[1][2 * g + 0], al1, wf[g][0], wf[g][2]);
            mma16816(acc[1][2 * g + 1], al1, wf[g][1], wf[g][3]);
        }
#pragma unroll
        for (int g = 0; g < 4; g++) ldsm4(wf[g], wbase + WBUF_SZ + woff + g * 16 * WSTR_B);
#pragma unroll
        for (int g = 0; g < 4; g++) {
            mma16816(acc[0][2 * g + 0], ah0, wf[g][0], wf[g][2]);
            mma16816(acc[0][2 * g + 1], ah0, wf[g][1], wf[g][3]);
            mma16816(acc[1][2 * g + 0], ah1, wf[g][0], wf[g][2]);
            mma16816(acc[1][2 * g + 1], ah1, wf[g][1], wf[g][3]);
        }
    }
}

// full GEMM: acc[128x256] = A @ W^T (3-term split), W double-buffered
__device__ __forceinline__ void gemm_mma(uint32_t sb,
                                         const __nv_bfloat16* Wh, const __nv_bfloat16* Wl,
                                         float (&acc)[2][8][4],
                                         int m0, int n0, int lane, int tid) {
#pragma unroll
    for (int i = 0; i < 2; i++)
#pragma unroll
        for (int j = 0; j < 8; j++)
#pragma unroll
            for (int q = 0; q < 4; q++) acc[i][j][q] = 0.f;

    stage_chunk(sb, (const char*)Wh, (const char*)Wl, 0, 0, tid);
#pragma unroll 1
    for (int ck = 0; ck < 8; ck++) {
        if (ck < 7) {
            stage_chunk(sb, (const char*)Wh, (const char*)Wl, ck + 1, (ck + 1) & 1, tid);
            CP_WAIT1();
        } else {
            CP_WAIT0();
        }
        __syncthreads();
        compute_chunk(sb, ck & 1, ck, acc, m0, n0, lane);
        __syncthreads();
    }
}

// split fp32 pair -> bf16 hi/lo and store into A buffers at (row, k)
__device__ __forceinline__ void sts_split2(char* smem, int row, int k, float y0, float y1) {
    __nv_bfloat16 h0 = __float2bfloat16(y0);
    __nv_bfloat16 l0 = __float2bfloat16(y0 - __bfloat162float(h0));
    __nv_bfloat16 h1 = __float2bfloat16(y1);
    __nv_bfloat16 l1 = __float2bfloat16(y1 - __bfloat162float(h1));
    uint32_t off = row * ASTR_B + k * 2;
    *reinterpret_cast<__nv_bfloat162*>(smem + A_HI + off) = __halves2bfloat162(h0, h1);
    *reinterpret_cast<__nv_bfloat162*>(smem + A_LO + off) = __halves2bfloat162(l0, l1);
}

// ---------------------------------------------------------------------------
__global__ void __launch_bounds__(NTH, 1)
fused_mma(const float* __restrict__ x,
          const int* __restrict__ bids,
          const float* __restrict__ b2,
          const float* __restrict__ b3,
          float* __restrict__ out, int N) {
    extern __shared__ __align__(16) char smem[];
    const uint32_t sb = smem_u32(smem);
    const int tid = threadIdx.x;
    const int lane = tid & 31, w = tid >> 5;
    const int warp_m = w >> 2, warp_n = w & 3;
    const int m0 = warp_m * 32, n0 = warp_n * 64;
    const int lgrp = lane >> 2, lq = lane & 3;
    const int row0 = blockIdx.x * TILE_M;

    // ---- build A (hi/lo bf16) from x tile [128 x 256] ----
#pragma unroll 4
    for (int i = 0; i < 16; i++) {
        int idx = tid + NTH * i;            // 8192 float4 groups
        int m = idx >> 6, c4 = idx & 63;
        int row = row0 + m;
        float4 v = (row < N) ? reinterpret_cast<const float4*>(x)[(size_t)row * 64 + c4]
                             : make_float4(0.f, 0.f, 0.f, 0.f);
        sts_split2(smem, m, c4 * 4 + 0, v.x, v.y);
        sts_split2(smem, m, c4 * 4 + 2, v.z, v.w);
    }

    float acc[2][8][4];

    // ================= GEMM1 + layernorm/FiLM/relu =================
    gemm_mma(sb, d_W1h, d_W1l, acc, m0, n0, lane, tid);
    {
        // per-row partial sums
#pragma unroll
        for (int mi = 0; mi < 2; mi++)
#pragma unroll
            for (int half = 0; half < 2; half++) {
                float s = 0.f, ss = 0.f;
#pragma unroll
                for (int j = 0; j < 8; j++) {
                    float v0 = acc[mi][j][half * 2 + 0];
                    float v1 = acc[mi][j][half * 2 + 1];
                    s += v0 + v1;
                    ss = fmaf(v0, v0, fmaf(v1, v1, ss));
                }
                s  += __shfl_xor_sync(0xffffffffu, s, 1);
                s  += __shfl_xor_sync(0xffffffffu, s, 2);
                ss += __shfl_xor_sync(0xffffffffu, ss, 1);
                ss += __shfl_xor_sync(0xffffffffu, ss, 2);
                if (lq == 0) {
                    int r = m0 + mi * 16 + half * 8 + lgrp;
                    *reinterpret_cast<float2*>(smem + PART + (r * 4 + warp_n) * 8) =
                        make_float2(s, ss);
                }
            }
        __syncthreads();
        if (tid < 128) {
            float s = 0.f, ss = 0.f;
#pragma unroll
            for (int q = 0; q < 4; q++) {
                float2 p = *reinterpret_cast<float2*>(smem + PART + (tid * 4 + q) * 8);
                s += p.x;
                ss += p.y;
            }
            float mu = s * (1.f / 256.f);
            float var = ss * (1.f / 256.f) - mu * mu;
            float rstd = rsqrtf(var + 1e-5f);
            *reinterpret_cast<float2*>(smem + STAT + tid * 8) = make_float2(mu, rstd);
            int row = row0 + tid;
            *reinterpret_cast<int*>(smem + SBID + tid * 4) = (row < N) ? bids[row] : 0;
        }
        __syncthreads();
        // apply: y = relu(gamma*(v-mu)*rstd + beta), write bf16 split to A
#pragma unroll
        for (int mi = 0; mi < 2; mi++)
#pragma unroll
            for (int half = 0; half < 2; half++) {
                int r = m0 + mi * 16 + half * 8 + lgrp;
                float2 st = *reinterpret_cast<float2*>(smem + STAT + r * 8);
                int bid = *reinterpret_cast<int*>(smem + SBID + r * 4);
                const float* gp = d_GAMMA + (size_t)bid * H_DIM;
                const float* bp = d_BETA  + (size_t)bid * H_DIM;
#pragma unroll
                for (int j = 0; j < 8; j++) {
                    int c = n0 + j * 8 + lq * 2;
                    float2 g2 = *reinterpret_cast<const float2*>(gp + c);
                    float2 be = *reinterpret_cast<const float2*>(bp + c);
                    float y0 = fmaxf(fmaf((acc[mi][j][half * 2 + 0] - st.x) * st.y, g2.x, be.x), 0.f);
                    float y1 = fmaxf(fmaf((acc[mi][j][half * 2 + 1] - st.x) * st.y, g2.y, be.y), 0.f);
                    sts_split2(smem, r, c, y0, y1);
                }
            }
    }

    // ================= GEMM2 + relu + b2 =================
    gemm_mma(sb, d_W2h, d_W2l, acc, m0, n0, lane, tid);
    {
        __syncthreads();  // all MMAs done before overwriting A
#pragma unroll
        for (int mi = 0; mi < 2; mi++)
#pragma unroll
            for (int half = 0; half < 2; half++) {
                int r = m0 + mi * 16 + half * 8 + lgrp;
#pragma unroll
                for (int j = 0; j < 8; j++) {
                    int c = n0 + j * 8 + lq * 2;
                    float2 bb = *reinterpret_cast<const float2*>(b2 + c);
                    float y0 = fmaxf(acc[mi][j][half * 2 + 0] + bb.x, 0.f);
                    float y1 = fmaxf(acc[mi][j][half * 2 + 1] + bb.y, 0.f);
                    sts_split2(smem, r, c, y0, y1);
                }
            }
    }

    // ================= GEMM3 (two 256-col halves) + b3 -> out =================
#pragma unroll 1
    for (int hf = 0; hf < 2; hf++) {
        gemm_mma(sb, d_W3h + (size_t)hf * 256 * K_DIM, d_W3l + (size_t)hf * 256 * K_DIM,
                 acc, m0, n0, lane, tid);
#pragma unroll
        for (int mi = 0; mi < 2; mi++)
#pragma unroll
            for (int half = 0; half < 2; half++) {
                int r = m0 + mi * 16 + half * 8 + lgrp;
                int row = row0 + r;
                if (row < N) {
                    float* op = out + (size_t)row * OUT_DIM + hf * 256;
#pragma unroll
                    for (int j = 0; j < 8; j++) {
                        int c = n0 + j * 8 + lq * 2;
                        float2 bb = *reinterpret_cast<const float2*>(b3 + hf * 256 + c);
                        float2 o2;
                        o2.x = acc[mi][j][half * 2 + 0] + bb.x;
                        o2.y = acc[mi][j][half * 2 + 1] + bb.y;
                        *reinterpret_cast<float2*>(op + c) = o2;
                    }
                }
            }
    }
}

// ---------------------------------------------------------------------------
extern "C" void kernel_launch(void* const* d_in, const int* in_sizes, int n_in,
                              void* d_out, int out_size) {
    const float* x         = (const float*)d_in[0];
    const float* cond      = (const float*)d_in[1];
    const int*   batch_ids = (const int*)  d_in[2];
    const float* v_cond    = (const float*)d_in[3];
    const float* g_cond    = (const float*)d_in[4];
    const float* b_cond    = (const float*)d_in[5];
    const float* v1        = (const float*)d_in[6];
    const float* g1        = (const float*)d_in[7];
    const float* v2        = (const float*)d_in[8];
    const float* g2        = (const float*)d_in[9];
    const float* b2        = (const float*)d_in[10];
    const float* v3        = (const float*)d_in[11];
    const float* g3        = (const float*)d_in[12];
    const float* b3        = (const float*)d_in[13];
    float* out = (float*)d_out;

    int N = in_sizes[0] / K_DIM;

    wn_kernel<<<OUT_DIM, 256>>>(v_cond, g_cond, 0);
    wn_kernel<<<H_DIM,   256>>>(v1, g1, 1);
    wn_kernel<<<H_DIM,   256>>>(v2, g2, 2);
    wn_kernel<<<OUT_DIM, 256>>>(v3, g3, 3);
    film_kernel<<<G_DIM, 256>>>(cond, b_cond);

    cudaFuncSetAttribute(fused_mma, cudaFuncAttributeMaxDynamicSharedMemorySize, SMEM_TOTAL);
    int grid = (N + TILE_M - 1) / TILE_M;
    fused_mma<<<grid, NTH, SMEM_TOTAL>>>(x, batch_ids, b2, b3, out, N);
}

// round 7
// speedup vs baseline: 3.1420x; 1.1023x over previous
#include <cuda_runtime.h>
#include <cuda_bf16.h>
#include <math.h>
#include <stdint.h>

#define K_DIM 256
#define H_DIM 256
#define OUT_DIM 512
#define G_DIM 256
#define TILE_M 128
#define NTH 512
#define CHUNK_BYTES 32768     // one k32 chunk: [hi 16KB][lo 16KB]

// ---- smem layout (bytes) ----
#define ASTR_B 528            // 264 bf16 per A row
#define MBAR 0                // 2 mbarriers (16B)
#define A_HI 1024
#define A_LO (A_HI + 67584)   // 68608
#define WB   (A_LO + 67584)   // 136192 (128B aligned)
#define PART (WB + 2 * CHUNK_BYTES)  // 201728: 128 rows x 4 warps x float2
#define STAT (PART + 4096)    // 205824: 128 x float2
#define SBID (STAT + 1024)    // 206848: 128 x int
#define SMEM_TOTAL 207360

// ---------------- global scratch ----------------
__device__ float d_Wc[OUT_DIM * K_DIM];
__device__ float d_GAMMA[G_DIM * H_DIM];
__device__ float d_BETA[G_DIM * H_DIM];
// weight "smem images": per 256-row part: 8 chunks x [hi 16KB | lo 16KB], quad-swizzled
__device__ __align__(128) uint8_t d_W1i[262144];
__device__ __align__(128) uint8_t d_W2i[262144];
__device__ __align__(128) uint8_t d_W3i[524288];

// ---------------- asm helpers ----------------
__device__ __forceinline__ uint32_t smem_u32(const void* p) {
    uint32_t a;
    asm("{ .reg .u64 t; cvta.to.shared.u64 t, %1; cvt.u32.u64 %0, t; }" : "=r"(a) : "l"(p));
    return a;
}
__device__ __forceinline__ void ldsm4(uint32_t (&r)[4], uint32_t a) {
    asm volatile("ldmatrix.sync.aligned.m8n8.x4.shared.b16 {%0,%1,%2,%3}, [%4];"
                 : "=r"(r[0]), "=r"(r[1]), "=r"(r[2]), "=r"(r[3]) : "r"(a));
}
__device__ __forceinline__ void mma16816(float* c, const uint32_t* a, uint32_t b0, uint32_t b1) {
    asm volatile("mma.sync.aligned.m16n8k16.row.col.f32.bf16.bf16.f32 "
                 "{%0,%1,%2,%3}, {%4,%5,%6,%7}, {%8,%9}, {%0,%1,%2,%3};"
                 : "+f"(c[0]), "+f"(c[1]), "+f"(c[2]), "+f"(c[3])
                 : "r"(a[0]), "r"(a[1]), "r"(a[2]), "r"(a[3]), "r"(b0), "r"(b1));
}
#define MBAR_INIT(mb, c) asm volatile("mbarrier.init.shared.b64 [%0], %1;" :: "r"(mb), "r"(c) : "memory")
__device__ __forceinline__ void mbar_wait(uint32_t mb, uint32_t parity) {
    asm volatile(
        "{\n\t.reg .pred P1;\n\tW_%=:\n\t"
        "mbarrier.try_wait.parity.acquire.cta.shared::cta.b64 P1, [%0], %1, 0x989680;\n\t"
        "@P1 bra.uni D_%=;\n\tbra.uni W_%=;\n\tD_%=:\n\t}"
        :: "r"(mb), "r"(parity) : "memory");
}
// one 32KB bulk copy of a weight chunk into buf (tid 0 only)
__device__ __forceinline__ void issue_copy(uint32_t sb, int buf, const uint8_t* src, int tid) {
    if (tid == 0) {
        uint32_t mb = sb + MBAR + buf * 8;
        asm volatile("mbarrier.arrive.expect_tx.shared.b64 _, [%0], %1;"
                     :: "r"(mb), "r"(CHUNK_BYTES) : "memory");
        asm volatile("cp.async.bulk.shared::cta.global.mbarrier::complete_tx::bytes "
                     "[%0], [%1], %2, [%3];"
                     :: "r"(sb + WB + buf * CHUNK_BYTES), "l"(src), "r"(CHUNK_BYTES), "r"(mb)
                     : "memory");
    }
}

// ---------------------------------------------------------------------------
// prep: weight norm -> bf16 hi/lo split -> swizzled chunk image
// image offset for (n, k, comp): chunk ck=k/32; quad q=(k%32)/8 swizzled by n
// ---------------------------------------------------------------------------
__global__ void wn_kernel(const float* __restrict__ v, const float* __restrict__ g, int which) {
    int r = blockIdx.x, t = threadIdx.x;
    float x = v[r * K_DIM + t];
    float ss = x * x;
#pragma unroll
    for (int o = 16; o; o >>= 1) ss += __shfl_xor_sync(0xffffffffu, ss, o);
    __shared__ float red[8];
    __shared__ float s_scale;
    if ((t & 31) == 0) red[t >> 5] = ss;
    __syncthreads();
    if (t == 0) {
        float tot = 0.f;
#pragma unroll
        for (int i = 0; i < 8; i++) tot += red[i];
        s_scale = g[r] / sqrtf(tot);
    }
    __syncthreads();
    float wv = x * s_scale;
    if (which == 0) { d_Wc[r * K_DIM + t] = wv; return; }
    uint8_t* img = (which == 1) ? d_W1i : (which == 2) ? d_W2i : d_W3i;
    int p = r >> 8, n = r & 255;
    img += (size_t)p * 262144;
    __nv_bfloat16 hi = __float2bfloat16(wv);
    __nv_bfloat16 lo = __float2bfloat16(wv - __bfloat162float(hi));
    int ck = t >> 5, kk = t & 31, q = kk >> 3, e = kk & 7;
    int qs = (q + (n >> 1)) & 3;
    size_t off = (size_t)ck * CHUNK_BYTES + n * 64 + qs * 16 + e * 2;
    *reinterpret_cast<__nv_bfloat16*>(img + off) = hi;
    *reinterpret_cast<__nv_bfloat16*>(img + off + 16384) = lo;
}

__global__ void film_kernel(const float* __restrict__ cond, const float* __restrict__ b_cond) {
    __shared__ float cs[K_DIM];
    int g = blockIdx.x, t = threadIdx.x;
    cs[t] = cond[g * K_DIM + t];
    __syncthreads();
    const float* w0 = d_Wc + (size_t)t * K_DIM;
    const float* w1 = d_Wc + (size_t)(t + 256) * K_DIM;
    float a0 = 0.f, a1 = 0.f;
#pragma unroll 8
    for (int k = 0; k < K_DIM; k++) {
        float c = cs[k];
        a0 = fmaf(c, w0[k], a0);
        a1 = fmaf(c, w1[k], a1);
    }
    d_GAMMA[g * H_DIM + t] = a0 + b_cond[t] + 1.0f;
    d_BETA[g * H_DIM + t]  = a1 + b_cond[t + 256];
}

// ---------------------------------------------------------------------------
// compute one 32-wide k chunk, 3-term bf16 split
// ---------------------------------------------------------------------------
__device__ __forceinline__ void compute_chunk(uint32_t sb, int buf, int ck,
                                              float (&acc)[2][8][4],
                                              int m0, int n0, int lane) {
    const uint32_t arow = m0 + (lane & 15);
    const uint32_t koff = (lane >> 4) * 8;
    const uint32_t wbase = sb + WB + buf * CHUNK_BYTES;
#pragma unroll
    for (int s = 0; s < 32; s += 16) {
        const int kg = ck * 32 + s;
        uint32_t ah0[4], ah1[4], al0[4], al1[4];
        uint32_t aoff = arow * ASTR_B + (kg + koff) * 2;
        ldsm4(ah0, sb + A_HI + aoff);
        ldsm4(ah1, sb + A_HI + aoff + 16 * ASTR_B);
        ldsm4(al0, sb + A_LO + aoff);
        ldsm4(al1, sb + A_LO + aoff + 16 * ASTR_B);

        const uint32_t q = (uint32_t)(s >> 3) + (lane >> 4);
        uint32_t wf[4][4];
#pragma unroll
        for (int g = 0; g < 4; g++) {
            uint32_t nr = n0 + g * 16 + (lane & 15);
            ldsm4(wf[g], wbase + nr * 64 + (((q + (nr >> 1)) & 3) << 4));
        }
#pragma unroll
        for (int g = 0; g < 4; g++) {
            mma16816(acc[0][2 * g + 0], ah0, wf[g][0], wf[g][2]);
            mma16816(acc[0][2 * g + 1], ah0, wf[g][1], wf[g][3]);
            mma16816(acc[1][2 * g + 0], ah1, wf[g][0], wf[g][2]);
            mma16816(acc[1][2 * g + 1], ah1, wf[g][1], wf[g][3]);
            mma16816(acc[0][2 * g + 0], al0, wf[g][0], wf[g][2]);
            mma16816(acc[0][2 * g + 1], al0, wf[g][1], wf[g][3]);
            mma16816(acc[1][2 * g + 0], al1, wf[g][0], wf[g][2]);
            mma16816(acc[1][2 * g + 1], al1, wf[g][1], wf[g][3]);
        }
#pragma unroll
        for (int g = 0; g < 4; g++) {
            uint32_t nr = n0 + g * 16 + (lane & 15);
            ldsm4(wf[g], wbase + 16384 + nr * 64 + (((q + (nr >> 1)) & 3) << 4));
        }
#pragma unroll
        for (int g = 0; g < 4; g++) {
            mma16816(acc[0][2 * g + 0], ah0, wf[g][0], wf[g][2]);
            mma16816(acc[0][2 * g + 1], ah0, wf[g][1], wf[g][3]);
            mma16816(acc[1][2 * g + 0], ah1, wf[g][0], wf[g][2]);
            mma16816(acc[1][2 * g + 1], ah1, wf[g][1], wf[g][3]);
        }
    }
}

// full GEMM over K=256 (8 chunks), double-buffered bulk copies.
// Pre-issues the first 2 chunks of Wnext during the tail of this GEMM.
__device__ __forceinline__ void run_gemm(uint32_t sb, const uint8_t* Wcur, const uint8_t* Wnext,
                                         float (&acc)[2][8][4],
                                         int m0, int n0, int lane, int tid, int (&wph)[2]) {
#pragma unroll
    for (int i = 0; i < 2; i++)
#pragma unroll
        for (int j = 0; j < 8; j++)
#pragma unroll
            for (int qq = 0; qq < 4; qq++) acc[i][j][qq] = 0.f;

    __syncthreads();  // order prior A-tile writes before compute
#pragma unroll 1
    for (int ck = 0; ck < 8; ck++) {
        int b = ck & 1;
        mbar_wait(sb + MBAR + b * 8, wph[b] & 1);
        wph[b] ^= 1;
        compute_chunk(sb, b, ck, acc, m0, n0, lane);
        __syncthreads();  // all warps done with buf b before refill
        if (ck < 6)       issue_copy(sb, b, Wcur + (size_t)(ck + 2) * CHUNK_BYTES, tid);
        else if (Wnext)   issue_copy(sb, b, Wnext + (size_t)(ck - 6) * CHUNK_BYTES, tid);
    }
}

// split fp32 pair -> bf16 hi/lo into A buffers at (row, k)
__device__ __forceinline__ void sts_split2(char* smem, int row, int k, float y0, float y1) {
    __nv_bfloat16 h0 = __float2bfloat16(y0);
    __nv_bfloat16 l0 = __float2bfloat16(y0 - __bfloat162float(h0));
    __nv_bfloat16 h1 = __float2bfloat16(y1);
    __nv_bfloat16 l1 = __float2bfloat16(y1 - __bfloat162float(h1));
    uint32_t off = row * ASTR_B + k * 2;
    *reinterpret_cast<__nv_bfloat162*>(smem + A_HI + off) = __halves2bfloat162(h0, h1);
    *reinterpret_cast<__nv_bfloat162*>(smem + A_LO + off) = __halves2bfloat162(l0, l1);
}

// ---------------------------------------------------------------------------
__global__ void __launch_bounds__(NTH, 1)
fused_mma(const float* __restrict__ x,
          const int* __restrict__ bids,
          const float* __restrict__ b2,
          const float* __restrict__ b3,
          float* __restrict__ out, int N) {
    extern __shared__ __align__(128) char smem[];
    const uint32_t sb = smem_u32(smem);
    const int tid = threadIdx.x;
    const int lane = tid & 31, w = tid >> 5;
    const int warp_m = w >> 2, warp_n = w & 3;
    const int m0 = warp_m * 32, n0 = warp_n * 64;
    const int lgrp = lane >> 2, lq = lane & 3;
    const int row0 = blockIdx.x * TILE_M;

    if (tid == 0) {
        MBAR_INIT(sb + MBAR + 0, 1);
        MBAR_INIT(sb + MBAR + 8, 1);
    }
    __syncthreads();
    // kick off W1 chunks 0,1 immediately (overlap with X staging)
    issue_copy(sb, 0, d_W1i, tid);
    issue_copy(sb, 1, d_W1i + CHUNK_BYTES, tid);

    // ---- build A (hi/lo bf16) from x tile [128 x 256] ----
#pragma unroll 4
    for (int i = 0; i < 16; i++) {
        int idx = tid + NTH * i;
        int m = idx >> 6, c4 = idx & 63;
        int row = row0 + m;
        float4 v = (row < N) ? reinterpret_cast<const float4*>(x)[(size_t)row * 64 + c4]
                             : make_float4(0.f, 0.f, 0.f, 0.f);
        sts_split2(smem, m, c4 * 4 + 0, v.x, v.y);
        sts_split2(smem, m, c4 * 4 + 2, v.z, v.w);
    }

    float acc[2][8][4];
    int wph[2] = {0, 0};

    // ================= GEMM1 + layernorm/FiLM/relu =================
    run_gemm(sb, d_W1i, d_W2i, acc, m0, n0, lane, tid, wph);
    {
#pragma unroll
        for (int mi = 0; mi < 2; mi++)
#pragma unroll
            for (int half = 0; half < 2; half++) {
                float s = 0.f, ss = 0.f;
#pragma unroll
                for (int j = 0; j < 8; j++) {
                    float v0 = acc[mi][j][half * 2 + 0];
                    float v1 = acc[mi][j][half * 2 + 1];
                    s += v0 + v1;
                    ss = fmaf(v0, v0, fmaf(v1, v1, ss));
                }
                s  += __shfl_xor_sync(0xffffffffu, s, 1);
                s  += __shfl_xor_sync(0xffffffffu, s, 2);
                ss += __shfl_xor_sync(0xffffffffu, ss, 1);
                ss += __shfl_xor_sync(0xffffffffu, ss, 2);
                if (lq == 0) {
                    int r = m0 + mi * 16 + half * 8 + lgrp;
                    *reinterpret_cast<float2*>(smem + PART + (r * 4 + warp_n) * 8) =
                        make_float2(s, ss);
                }
            }
        __syncthreads();
        if (tid < 128) {
            float s = 0.f, ss = 0.f;
#pragma unroll
            for (int qq = 0; qq < 4; qq++) {
                float2 p = *reinterpret_cast<float2*>(smem + PART + (tid * 4 + qq) * 8);
                s += p.x;
                ss += p.y;
            }
            float mu = s * (1.f / 256.f);
            float var = ss * (1.f / 256.f) - mu * mu;
            float rstd = rsqrtf(var + 1e-5f);
            *reinterpret_cast<float2*>(smem + STAT + tid * 8) = make_float2(mu, rstd);
            int row = row0 + tid;
            *reinterpret_cast<int*>(smem + SBID + tid * 4) = (row < N) ? bids[row] : 0;
        }
        __syncthreads();
#pragma unroll
        for (int mi = 0; mi < 2; mi++)
#pragma unroll
            for (int half = 0; half < 2; half++) {
                int r = m0 + mi * 16 + half * 8 + lgrp;
                float2 st = *reinterpret_cast<float2*>(smem + STAT + r * 8);
                int bid = *reinterpret_cast<int*>(smem + SBID + r * 4);
                const float* gp = d_GAMMA + (size_t)bid * H_DIM;
                const float* bp = d_BETA  + (size_t)bid * H_DIM;
#pragma unroll
                for (int j = 0; j < 8; j++) {
                    int c = n0 + j * 8 + lq * 2;
                    float2 g2 = *reinterpret_cast<const float2*>(gp + c);
                    float2 be = *reinterpret_cast<const float2*>(bp + c);
                    float y0 = fmaxf(fmaf((acc[mi][j][half * 2 + 0] - st.x) * st.y, g2.x, be.x), 0.f);
                    float y1 = fmaxf(fmaf((acc[mi][j][half * 2 + 1] - st.x) * st.y, g2.y, be.y), 0.f);
                    sts_split2(smem, r, c, y0, y1);
                }
            }
    }

    // ================= GEMM2 + relu + b2 =================
    run_gemm(sb, d_W2i, d_W3i, acc, m0, n0, lane, tid, wph);
    {
#pragma unroll
        for (int mi = 0; mi < 2; mi++)
#pragma unroll
            for (int half = 0; half < 2; half++) {
                int r = m0 + mi * 16 + half * 8 + lgrp;
#pragma unroll
                for (int j = 0; j < 8; j++) {
                    int c = n0 + j * 8 + lq * 2;
                    float2 bb = *reinterpret_cast<const float2*>(b2 + c);
                    float y0 = fmaxf(acc[mi][j][half * 2 + 0] + bb.x, 0.f);
                    float y1 = fmaxf(acc[mi][j][half * 2 + 1] + bb.y, 0.f);
                    sts_split2(smem, r, c, y0, y1);
                }
            }
    }

    // ================= GEMM3 (two 256-col halves) + b3 -> out =================
#pragma unroll 1
    for (int hf = 0; hf < 2; hf++) {
        const uint8_t* Wnext = (hf == 0) ? d_W3i + 262144 : nullptr;
        run_gemm(sb, d_W3i + (size_t)hf * 262144, Wnext, acc, m0, n0, lane, tid, wph);
#pragma unroll
        for (int mi = 0; mi < 2; mi++)
#pragma unroll
            for (int half = 0; half < 2; half++) {
                int r = m0 + mi * 16 + half * 8 + lgrp;
                int row = row0 + r;
                if (row < N) {
                    float* op = out + (size_t)row * OUT_DIM + hf * 256;
#pragma unroll
                    for (int j = 0; j < 8; j++) {
                        int c = n0 + j * 8 + lq * 2;
                        float2 bb = *reinterpret_cast<const float2*>(b3 + hf * 256 + c);
                        float2 o2;
                        o2.x = acc[mi][j][half * 2 + 0] + bb.x;
                        o2.y = acc[mi][j][half * 2 + 1] + bb.y;
                        *reinterpret_cast<float2*>(op + c) = o2;
                    }
                }
            }
    }
}

// ---------------------------------------------------------------------------
extern "C" void kernel_launch(void* const* d_in, const int* in_sizes, int n_in,
                              void* d_out, int out_size) {
    const float* x         = (const float*)d_in[0];
    const float* cond      = (const float*)d_in[1];
    const int*   batch_ids = (const int*)  d_in[2];
    const float* v_cond    = (const float*)d_in[3];
    const float* g_cond    = (const float*)d_in[4];
    const float* b_cond    = (const float*)d_in[5];
    const float* v1        = (const float*)d_in[6];
    const float* g1        = (const float*)d_in[7];
    const float* v2        = (const float*)d_in[8];
    const float* g2        = (const float*)d_in[9];
    const float* b2        = (const float*)d_in[10];
    const float* v3        = (const float*)d_in[11];
    const float* g3        = (const float*)d_in[12];
    const float* b3        = (const float*)d_in[13];
    float* out = (float*)d_out;

    int N = in_sizes[0] / K_DIM;

    wn_kernel<<<OUT_DIM, 256>>>(v_cond, g_cond, 0);
    wn_kernel<<<H_DIM,   256>>>(v1, g1, 1);
    wn_kernel<<<H_DIM,   256>>>(v2, g2, 2);
    wn_kernel<<<OUT_DIM, 256>>>(v3, g3, 3);
    film_kernel<<<G_DIM, 256>>>(cond, b_cond);

    cudaFuncSetAttribute(fused_mma, cudaFuncAttributeMaxDynamicSharedMemorySize, SMEM_TOTAL);
    int grid = (N + TILE_M - 1) / TILE_M;
    fused_mma<<<grid, NTH, SMEM_TOTAL>>>(x, batch_ids, b2, b3, out, N);
}